// round 8
// baseline (speedup 1.0000x reference)
#include <cuda_runtime.h>
#include <cuda_fp16.h>
#include <cstdint>

#define CIN     32
#define COUT    32
#define KVOL    27
#define WARPS   16
#define THREADS 512
#define NSTAGE  8
#define LEAD    6
#define ROWS_W  16
#define SLICE   1024                    // 16 rows * 64 B
#define W_TAP   2048
#define WBYTES  (KVOL * W_TAP)          // 55296
#define SMEM_TOTAL (WBYTES + WARPS * NSTAGE * SLICE)   // 186368
#define CAP     1000000

// K-permuted fp16 feature table (64 MB device scratch)
__device__ __align__(16) __half g_feath[(size_t)CAP * 32];
__device__ int g_valid_is_u8;

__global__ void detect_valid_dtype(const unsigned char* __restrict__ v, int nbytes) {
    int nz = 0;
    for (int i = threadIdx.x; i < nbytes; i += blockDim.x)
        if ((i & 3) && v[i]) nz = 1;
    if (__syncthreads_or(nz) && threadIdx.x == 0) g_valid_is_u8 = 1;
}

__device__ __forceinline__ uint32_t smem_u32(const void* p) {
    uint32_t a;
    asm("{ .reg .u64 t; cvta.to.shared.u64 t, %1; cvt.u32.u64 %0, t; }" : "=r"(a) : "l"(p));
    return a;
}
__device__ __forceinline__ void cp16(uint32_t dst, const void* src, uint32_t nbytes) {
    asm volatile("cp.async.cg.shared.global [%0], [%1], 16, %2;"
                 :: "r"(dst), "l"(src), "r"(nbytes) : "memory");
}
#define CP_COMMIT() asm volatile("cp.async.commit_group;" ::: "memory")
#define CP_WAIT6()  asm volatile("cp.async.wait_group 6;" ::: "memory")

__device__ __forceinline__ uint32_t h2pack(float a, float b) {
    __half2 h = __floats2half2_rn(a, b);
    return *(uint32_t*)&h;
}
__device__ __forceinline__ void mma_f16(float& d0, float& d1, float& d2, float& d3,
                                        uint32_t a0, uint32_t a1, uint32_t a2, uint32_t a3,
                                        uint32_t b0, uint32_t b1) {
    asm volatile(
        "mma.sync.aligned.m16n8k16.row.col.f32.f16.f16.f32 "
        "{%0,%1,%2,%3}, {%4,%5,%6,%7}, {%8,%9}, {%0,%1,%2,%3};"
        : "+f"(d0), "+f"(d1), "+f"(d2), "+f"(d3)
        : "r"(a0), "r"(a1), "r"(a2), "r"(a3), "r"(b0), "r"(b1));
}

// prepass: identical permuted fp16 layout to R7 (validated)
__global__ void prepass(const float* __restrict__ feat, int N) {
    int stride = gridDim.x * blockDim.x;
    int total = N * 8;
    for (int i = blockIdx.x * blockDim.x + threadIdx.x; i < total; i += stride) {
        int n = i >> 3, s = i & 7;
        int tig = s >> 1, kc = s & 1;
        const float* src = feat + (size_t)n * 32 + kc * 16 + 2 * tig;
        uint2 o;
        o.x = h2pack(src[0], src[1]);
        o.y = h2pack(src[8], src[9]);
        ((uint2*)g_feath)[(size_t)n * 8 + tig * 2 + kc] = o;
    }
}

struct Pref { int idx0, idx1; uint32_t n0, n1; };

// ---------------- main kernel ----------------
__global__ void __launch_bounds__(THREADS, 1)
spconv_mma(const float* __restrict__ weight,
           const float* __restrict__ bias,
           const int* __restrict__ kidx,
           const unsigned char* __restrict__ kvalid,
           float* __restrict__ out,
           int N)
{
    extern __shared__ __align__(16) char smem[];
    const uint32_t sb = smem_u32(smem);

    const int tid  = threadIdx.x;
    const int w    = tid >> 5;
    const int lane = tid & 31;
    const int gid  = lane >> 2;
    const int tig  = lane & 3;
    const int r8   = lane >> 2;
    const int ch   = lane & 3;
    const bool u8  = (g_valid_is_u8 != 0);
    const int* kvalid32 = (const int*)kvalid;

    // pack fp16 B fragments (validated layout, R7)
    for (int i = tid; i < KVOL * 512; i += THREADS) {
        int tap = i >> 9, d = i & 511;
        int p = d >> 7, ln = (d >> 2) & 31, q = d & 3;
        int kc = p >> 1;
        int nt = (p & 1) * 2 + (q >> 1);
        int tg = ln & 3, gd = ln >> 2;
        int k = kc * 16 + 2 * tg + ((q & 1) ? 8 : 0);
        const float* wrow = weight + (size_t)tap * 1024;
        ((uint32_t*)smem)[(size_t)tap * 512 + d] =
            h2pack(wrow[k * 32 + nt * 8 + gd], wrow[(k + 1) * 32 + nt * 8 + gd]);
    }
    __syncthreads();

    float2 bb[4];
    #pragma unroll
    for (int nt = 0; nt < 4; nt++) {
        bb[nt].x = bias[nt * 8 + tig * 2 + 0];
        bb[nt].y = bias[nt * 8 + tig * 2 + 1];
    }

    const int ntiles = (N + ROWS_W - 1) / ROWS_W;
    const int TW     = gridDim.x * WARPS;
    const int gw     = blockIdx.x * WARPS + w;

    int myT = 0;
    for (int t = gw; t < ntiles; t += TW) myT++;
    const int total = myT * KVOL;
    if (total == 0) return;

    const uint32_t aBase = sb + WBYTES + (uint32_t)(w * NSTAGE) * SLICE;
    const char*    fbase = (const char*)g_feath;

    const uint32_t dst0 = (uint32_t)r8 * 64 + (uint32_t)ch * 16;
    const uint32_t dst1 = dst0 + 512;

    // idx cursor (advances one job per call)
    int lS = gw, lTap = 0;
    auto load_idx = [&](Pref& P) {
        P.idx0 = 0; P.idx1 = 0; P.n0 = 0; P.n1 = 0;
        int g0 = lS * ROWS_W + r8, g1 = g0 + 8;
        if (lS < ntiles) {
            size_t o = (size_t)lTap * N;
            if (g0 < N) {
                P.idx0 = kidx[o + g0];
                P.n0 = (u8 ? (kvalid[o + g0] != 0) : (kvalid32[o + g0] != 0)) ? 16u : 0u;
            }
            if (g1 < N) {
                P.idx1 = kidx[o + g1];
                P.n1 = (u8 ? (kvalid[o + g1] != 0) : (kvalid32[o + g1] != 0)) ? 16u : 0u;
            }
        }
        if (++lTap == KVOL) { lTap = 0; lS += TW; }
    };
    auto issue = [&](const Pref& P, int stage) {
        uint32_t ab = aBase + (uint32_t)stage * SLICE;
        cp16(ab + dst0, fbase + ((size_t)(uint32_t)P.idx0 << 6) + (ch << 4), P.n0);
        cp16(ab + dst1, fbase + ((size_t)(uint32_t)P.idx1 << 6) + (ch << 4), P.n1);
    };

    // ---- prologue: issue jobs 0..LEAD-1, preload idx for jobs LEAD, LEAD+1 ----
    {
        Pref T;
        #pragma unroll
        for (int j = 0; j < LEAD; j++) {
            load_idx(T);
            issue(T, j);
            CP_COMMIT();
        }
    }
    Pref P[2];
    load_idx(P[0]);   // job LEAD
    load_idx(P[1]);   // job LEAD+1   (cursor now at LEAD+2)

    if (total < NSTAGE)   // never taken for N=1M (total>=27), safety for tiny N
        asm volatile("cp.async.wait_all;" ::: "memory");

    int ctap = 0, cS = gw;
    float acc[4][4];
    #pragma unroll
    for (int nt = 0; nt < 4; nt++)
        #pragma unroll
        for (int r = 0; r < 4; r++) acc[nt][r] = 0.0f;

    for (int jl = 0; jl < total; jl++) {
        CP_WAIT6();
        __syncwarp();

        // issue gather for job jl+LEAD (idx loaded 2 iterations ago)
        if (jl + LEAD < total) issue(P[jl & 1], (jl + LEAD) & (NSTAGE - 1));
        CP_COMMIT();

        // refill this Pref slot with idx for job jl+LEAD+2
        if (jl + LEAD + 2 < total) load_idx(P[jl & 1]);

        const char* Ab = (const char*)smem + WBYTES
                       + (size_t)(w * NSTAGE + (jl & (NSTAGE - 1))) * SLICE;

        // A fragments: 2x LDS.128, contiguous, conflict-free
        uint4 L = *(const uint4*)(Ab + (size_t)gid * 64 + tig * 16);
        uint4 M = *(const uint4*)(Ab + (size_t)(gid + 8) * 64 + tig * 16);

        const uint4* wp = (const uint4*)(smem + (size_t)ctap * W_TAP);

        #pragma unroll
        for (int kc = 0; kc < 2; kc++) {
            uint4 bf0 = wp[(kc * 2 + 0) * 32 + lane];
            uint4 bf1 = wp[(kc * 2 + 1) * 32 + lane];
            uint32_t a0 = kc ? L.z : L.x;
            uint32_t a2 = kc ? L.w : L.y;
            uint32_t a1 = kc ? M.z : M.x;
            uint32_t a3 = kc ? M.w : M.y;
            mma_f16(acc[0][0], acc[0][1], acc[0][2], acc[0][3], a0, a1, a2, a3, bf0.x, bf0.y);
            mma_f16(acc[1][0], acc[1][1], acc[1][2], acc[1][3], a0, a1, a2, a3, bf0.z, bf0.w);
            mma_f16(acc[2][0], acc[2][1], acc[2][2], acc[2][3], a0, a1, a2, a3, bf1.x, bf1.y);
            mma_f16(acc[3][0], acc[3][1], acc[3][2], acc[3][3], a0, a1, a2, a3, bf1.z, bf1.w);
        }

        if (++ctap == KVOL) {
            int gr = cS * ROWS_W + gid;
            #pragma unroll
            for (int nt = 0; nt < 4; nt++) {
                int col = nt * 8 + tig * 2;
                if (gr < N) {
                    float2 o = { acc[nt][0] + bb[nt].x, acc[nt][1] + bb[nt].y };
                    *(float2*)(out + (size_t)gr * COUT + col) = o;
                }
                if (gr + 8 < N) {
                    float2 o = { acc[nt][2] + bb[nt].x, acc[nt][3] + bb[nt].y };
                    *(float2*)(out + (size_t)(gr + 8) * COUT + col) = o;
                }
                acc[nt][0] = acc[nt][1] = acc[nt][2] = acc[nt][3] = 0.0f;
            }
            ctap = 0;
            cS += TW;
        }
    }
}

extern "C" void kernel_launch(void* const* d_in, const int* in_sizes, int n_in,
                              void* d_out, int out_size) {
    const float*         feat   = (const float*)d_in[0];          // [N, 32]
    const float*         weight = (const float*)d_in[1];          // [27, 32, 32]
    const float*         bias   = (const float*)d_in[2];          // [32]
    const int*           kidx   = (const int*)d_in[3];            // [27, N]
    const unsigned char* kvalid = (const unsigned char*)d_in[4];  // [27, N] bool
    float* out = (float*)d_out;

    const int N = in_sizes[0] / CIN;

    int sms = 148;
    cudaDeviceGetAttribute(&sms, cudaDevAttrMultiProcessorCount, 0);

    cudaFuncSetAttribute(spconv_mma, cudaFuncAttributeMaxDynamicSharedMemorySize, SMEM_TOTAL);

    detect_valid_dtype<<<1, 256>>>(kvalid, 2048);
    prepass<<<sms * 8, 256>>>(feat, N);
    spconv_mma<<<sms, THREADS, SMEM_TOTAL>>>(weight, bias, kidx, kvalid, out, N);
}

// round 9
// speedup vs baseline: 1.5124x; 1.5124x over previous
#include <cuda_runtime.h>
#include <cuda_fp16.h>
#include <cstdint>

#define CIN     32
#define COUT    32
#define KVOL    27
#define WARPS   24
#define THREADS 768
#define NSTAGE  4
#define ROWS_W  16
#define SLICE   1024                    // 16 rows * 64 B
#define W_TAP   2048
#define WBYTES  (KVOL * W_TAP)          // 55296
#define SMEM_TOTAL (WBYTES + WARPS * NSTAGE * SLICE)   // 153600
#define CAP     1000000

// K-permuted fp16 feature table (64 MB device scratch)
__device__ __align__(16) __half g_feath[(size_t)CAP * 32];
__device__ int g_valid_is_u8;

__device__ __forceinline__ uint32_t smem_u32(const void* p) {
    uint32_t a;
    asm("{ .reg .u64 t; cvta.to.shared.u64 t, %1; cvt.u32.u64 %0, t; }" : "=r"(a) : "l"(p));
    return a;
}
__device__ __forceinline__ void cp16(uint32_t dst, const void* src, uint32_t nbytes) {
    asm volatile("cp.async.cg.shared.global [%0], [%1], 16, %2;"
                 :: "r"(dst), "l"(src), "r"(nbytes) : "memory");
}
#define CP_COMMIT() asm volatile("cp.async.commit_group;" ::: "memory")
#define CP_WAIT2()  asm volatile("cp.async.wait_group 2;" ::: "memory")

__device__ __forceinline__ uint32_t h2pack(float a, float b) {
    __half2 h = __floats2half2_rn(a, b);
    return *(uint32_t*)&h;
}
__device__ __forceinline__ void mma_f16(float& d0, float& d1, float& d2, float& d3,
                                        uint32_t a0, uint32_t a1, uint32_t a2, uint32_t a3,
                                        uint32_t b0, uint32_t b1) {
    asm volatile(
        "mma.sync.aligned.m16n8k16.row.col.f32.f16.f16.f32 "
        "{%0,%1,%2,%3}, {%4,%5,%6,%7}, {%8,%9}, {%0,%1,%2,%3};"
        : "+f"(d0), "+f"(d1), "+f"(d2), "+f"(d3)
        : "r"(a0), "r"(a1), "r"(a2), "r"(a3), "r"(b0), "r"(b1));
}

// prepass: permuted fp16 table (validated layout) + valid-dtype detection (warp 0, block 0)
__global__ void prepass(const float* __restrict__ feat,
                        const unsigned char* __restrict__ kvalid, int N) {
    if (blockIdx.x == 0 && threadIdx.x < 32) {
        int nz = 0;
        for (int i = threadIdx.x; i < 4096; i += 32)
            if ((i & 3) && kvalid[i]) nz = 1;
        nz = __any_sync(0xffffffffu, nz);
        if (threadIdx.x == 0) g_valid_is_u8 = nz;
    }
    int stride = gridDim.x * blockDim.x;
    int total = N * 8;
    for (int i = blockIdx.x * blockDim.x + threadIdx.x; i < total; i += stride) {
        int n = i >> 3, s = i & 7;
        int tig = s >> 1, kc = s & 1;
        const float* src = feat + (size_t)n * 32 + kc * 16 + 2 * tig;
        uint2 o;
        o.x = h2pack(src[0], src[1]);
        o.y = h2pack(src[8], src[9]);
        ((uint2*)g_feath)[(size_t)n * 8 + tig * 2 + kc] = o;
    }
}

struct Pref { int idx0, idx1; uint32_t n0, n1; };

// ---------------- main kernel ----------------
__global__ void __launch_bounds__(THREADS, 1)
spconv_mma(const float* __restrict__ weight,
           const float* __restrict__ bias,
           const int* __restrict__ kidx,
           const unsigned char* __restrict__ kvalid,
           float* __restrict__ out,
           int N)
{
    extern __shared__ __align__(16) char smem[];
    const uint32_t sb = smem_u32(smem);

    const int tid  = threadIdx.x;
    const int w    = tid >> 5;
    const int lane = tid & 31;
    const int gid  = lane >> 2;
    const int tig  = lane & 3;
    const int r8   = lane >> 2;
    const int ch   = lane & 3;
    const bool u8  = (g_valid_is_u8 != 0);
    const int* kvalid32 = (const int*)kvalid;

    // pack fp16 B fragments (validated layout)
    for (int i = tid; i < KVOL * 512; i += THREADS) {
        int tap = i >> 9, d = i & 511;
        int p = d >> 7, ln = (d >> 2) & 31, q = d & 3;
        int kc = p >> 1;
        int nt = (p & 1) * 2 + (q >> 1);
        int tg = ln & 3, gd = ln >> 2;
        int k = kc * 16 + 2 * tg + ((q & 1) ? 8 : 0);
        const float* wrow = weight + (size_t)tap * 1024;
        ((uint32_t*)smem)[(size_t)tap * 512 + d] =
            h2pack(wrow[k * 32 + nt * 8 + gd], wrow[(k + 1) * 32 + nt * 8 + gd]);
    }
    __syncthreads();

    float2 bb[4];
    #pragma unroll
    for (int nt = 0; nt < 4; nt++) {
        bb[nt].x = bias[nt * 8 + tig * 2 + 0];
        bb[nt].y = bias[nt * 8 + tig * 2 + 1];
    }

    const int ntiles = (N + ROWS_W - 1) / ROWS_W;
    const int TW     = gridDim.x * WARPS;
    const int gw     = blockIdx.x * WARPS + w;

    int myT = 0;
    for (int t = gw; t < ntiles; t += TW) myT++;
    const int total = myT * KVOL;
    if (total == 0) return;

    const uint32_t aBase = sb + WBYTES + (uint32_t)(w * NSTAGE) * SLICE;
    const char*    fbase = (const char*)g_feath;

    const uint32_t dst0 = (uint32_t)r8 * 64 + (uint32_t)ch * 16;
    const uint32_t dst1 = dst0 + 512;

    auto load_idx = [&](int S, int tap, Pref& P) {
        P.idx0 = 0; P.idx1 = 0; P.n0 = 0; P.n1 = 0;
        int g0 = S * ROWS_W + r8, g1 = g0 + 8;
        if (S < ntiles) {
            size_t o = (size_t)tap * N;
            if (g0 < N) {
                P.idx0 = kidx[o + g0];
                P.n0 = (u8 ? (kvalid[o + g0] != 0) : (kvalid32[o + g0] != 0)) ? 16u : 0u;
            }
            if (g1 < N) {
                P.idx1 = kidx[o + g1];
                P.n1 = (u8 ? (kvalid[o + g1] != 0) : (kvalid32[o + g1] != 0)) ? 16u : 0u;
            }
        }
    };
    auto issue = [&](const Pref& P, int stage) {
        uint32_t ab = aBase + (uint32_t)stage * SLICE;
        cp16(ab + dst0, fbase + ((size_t)(uint32_t)P.idx0 << 6) + (ch << 4), P.n0);
        cp16(ab + dst1, fbase + ((size_t)(uint32_t)P.idx1 << 6) + (ch << 4), P.n1);
    };

    // ---- prologue: jobs 0..2 issued, idx(job3) prefetched ----
    Pref Pa;
    load_idx(gw, 0, Pa);
    issue(Pa, 0); CP_COMMIT();
    if (total > 1) { load_idx(gw, 1, Pa); issue(Pa, 1); }
    CP_COMMIT();
    if (total > 2) { load_idx(gw, 2, Pa); issue(Pa, 2); }
    CP_COMMIT();
    if (total > 3) load_idx(gw, 3, Pa);

    int ptap = 4, pS = gw;
    while (ptap >= KVOL) { ptap -= KVOL; pS += TW; }
    int ctap = 0, cS = gw;

    float acc[4][4];
    #pragma unroll
    for (int nt = 0; nt < 4; nt++)
        #pragma unroll
        for (int r = 0; r < 4; r++) acc[nt][r] = 0.0f;

    for (int jl = 0; jl < total; jl++) {
        CP_WAIT2();
        __syncwarp();

        if (jl + 3 < total) issue(Pa, (jl + 3) & (NSTAGE - 1));
        CP_COMMIT();

        if (jl + 4 < total) {
            load_idx(pS, ptap, Pa);
            if (++ptap == KVOL) { ptap = 0; pS += TW; }
        }

        const char* Ab = (const char*)smem + WBYTES
                       + (size_t)(w * NSTAGE + (jl & (NSTAGE - 1))) * SLICE;

        // A fragments: 2x LDS.128, contiguous, conflict-free
        uint4 L = *(const uint4*)(Ab + (size_t)gid * 64 + tig * 16);
        uint4 M = *(const uint4*)(Ab + (size_t)(gid + 8) * 64 + tig * 16);

        const uint4* wp = (const uint4*)(smem + (size_t)ctap * W_TAP);

        #pragma unroll
        for (int kc = 0; kc < 2; kc++) {
            uint4 bf0 = wp[(kc * 2 + 0) * 32 + lane];
            uint4 bf1 = wp[(kc * 2 + 1) * 32 + lane];
            uint32_t a0 = kc ? L.z : L.x;
            uint32_t a2 = kc ? L.w : L.y;
            uint32_t a1 = kc ? M.z : M.x;
            uint32_t a3 = kc ? M.w : M.y;
            mma_f16(acc[0][0], acc[0][1], acc[0][2], acc[0][3], a0, a1, a2, a3, bf0.x, bf0.y);
            mma_f16(acc[1][0], acc[1][1], acc[1][2], acc[1][3], a0, a1, a2, a3, bf0.z, bf0.w);
            mma_f16(acc[2][0], acc[2][1], acc[2][2], acc[2][3], a0, a1, a2, a3, bf1.x, bf1.y);
            mma_f16(acc[3][0], acc[3][1], acc[3][2], acc[3][3], a0, a1, a2, a3, bf1.z, bf1.w);
        }

        if (++ctap == KVOL) {
            int gr = cS * ROWS_W + gid;
            #pragma unroll
            for (int nt = 0; nt < 4; nt++) {
                int col = nt * 8 + tig * 2;
                if (gr < N) {
                    float2 o = { acc[nt][0] + bb[nt].x, acc[nt][1] + bb[nt].y };
                    *(float2*)(out + (size_t)gr * COUT + col) = o;
                }
                if (gr + 8 < N) {
                    float2 o = { acc[nt][2] + bb[nt].x, acc[nt][3] + bb[nt].y };
                    *(float2*)(out + (size_t)(gr + 8) * COUT + col) = o;
                }
                acc[nt][0] = acc[nt][1] = acc[nt][2] = acc[nt][3] = 0.0f;
            }
            ctap = 0;
            cS += TW;
        }
    }
}

extern "C" void kernel_launch(void* const* d_in, const int* in_sizes, int n_in,
                              void* d_out, int out_size) {
    const float*         feat   = (const float*)d_in[0];          // [N, 32]
    const float*         weight = (const float*)d_in[1];          // [27, 32, 32]
    const float*         bias   = (const float*)d_in[2];          // [32]
    const int*           kidx   = (const int*)d_in[3];            // [27, N]
    const unsigned char* kvalid = (const unsigned char*)d_in[4];  // [27, N] bool
    float* out = (float*)d_out;

    const int N = in_sizes[0] / CIN;

    int sms = 148;
    cudaDeviceGetAttribute(&sms, cudaDevAttrMultiProcessorCount, 0);

    cudaFuncSetAttribute(spconv_mma, cudaFuncAttributeMaxDynamicSharedMemorySize, SMEM_TOTAL);

    prepass<<<sms * 8, 256>>>(feat, kvalid, N);
    spconv_mma<<<sms, THREADS, SMEM_TOTAL>>>(weight, bias, kidx, kvalid, out, N);
}

// round 10
// speedup vs baseline: 1.8932x; 1.2517x over previous
#include <cuda_runtime.h>
#include <cuda_fp16.h>
#include <cstdint>

#define CIN     32
#define COUT    32
#define KVOL    27
#define WARPS   32
#define THREADS 1024
#define NSTAGE  4
#define ROWS_W  16
#define SLICE   1024                    // 16 rows * 64 B
#define W_TAP   2048
#define WBYTES  (KVOL * W_TAP)          // 55296
#define OFF_BIAS WBYTES
#define OFF_A   (WBYTES + 128)
#define SMEM_TOTAL (OFF_A + WARPS * NSTAGE * SLICE)    // 186496
#define CAP     1000000

// K-permuted fp16 feature table (64 MB device scratch)
__device__ __align__(16) __half g_feath[(size_t)CAP * 32];
__device__ int g_valid_is_u8;

__device__ __forceinline__ uint32_t smem_u32(const void* p) {
    uint32_t a;
    asm("{ .reg .u64 t; cvta.to.shared.u64 t, %1; cvt.u32.u64 %0, t; }" : "=r"(a) : "l"(p));
    return a;
}
__device__ __forceinline__ void cp16(uint32_t dst, const void* src, uint32_t nbytes) {
    asm volatile("cp.async.cg.shared.global [%0], [%1], 16, %2;"
                 :: "r"(dst), "l"(src), "r"(nbytes) : "memory");
}
#define CP_COMMIT() asm volatile("cp.async.commit_group;" ::: "memory")
#define CP_WAIT2()  asm volatile("cp.async.wait_group 2;" ::: "memory")

__device__ __forceinline__ uint32_t h2pack(float a, float b) {
    __half2 h = __floats2half2_rn(a, b);
    return *(uint32_t*)&h;
}
__device__ __forceinline__ void mma_f16(float& d0, float& d1, float& d2, float& d3,
                                        uint32_t a0, uint32_t a1, uint32_t a2, uint32_t a3,
                                        uint32_t b0, uint32_t b1) {
    asm volatile(
        "mma.sync.aligned.m16n8k16.row.col.f32.f16.f16.f32 "
        "{%0,%1,%2,%3}, {%4,%5,%6,%7}, {%8,%9}, {%0,%1,%2,%3};"
        : "+f"(d0), "+f"(d1), "+f"(d2), "+f"(d3)
        : "r"(a0), "r"(a1), "r"(a2), "r"(a3), "r"(b0), "r"(b1));
}

// prepass: permuted fp16 table (validated) + valid-dtype detection
__global__ void prepass(const float* __restrict__ feat,
                        const unsigned char* __restrict__ kvalid, int N) {
    if (blockIdx.x == 0 && threadIdx.x < 32) {
        int nz = 0;
        for (int i = threadIdx.x; i < 4096; i += 32)
            if ((i & 3) && kvalid[i]) nz = 1;
        nz = __any_sync(0xffffffffu, nz);
        if (threadIdx.x == 0) g_valid_is_u8 = nz;
    }
    int stride = gridDim.x * blockDim.x;
    int total = N * 8;
    for (int i = blockIdx.x * blockDim.x + threadIdx.x; i < total; i += stride) {
        int n = i >> 3, s = i & 7;
        int tig = s >> 1, kc = s & 1;
        const float* src = feat + (size_t)n * 32 + kc * 16 + 2 * tig;
        uint2 o;
        o.x = h2pack(src[0], src[1]);
        o.y = h2pack(src[8], src[9]);
        ((uint2*)g_feath)[(size_t)n * 8 + tig * 2 + kc] = o;
    }
}

struct Pref { int idx0, idx1; uint32_t n0, n1; };

// ---------------- main kernel ----------------
__global__ void __launch_bounds__(THREADS, 1)
spconv_mma(const float* __restrict__ weight,
           const float* __restrict__ bias,
           const int* __restrict__ kidx,
           const unsigned char* __restrict__ kvalid,
           float* __restrict__ out,
           int N)
{
    extern __shared__ __align__(16) char smem[];
    const uint32_t sb = smem_u32(smem);

    const int tid  = threadIdx.x;
    const int w    = tid >> 5;
    const int lane = tid & 31;
    const int gid  = lane >> 2;
    const int tig  = lane & 3;
    const int r8   = lane >> 2;
    const int ch   = lane & 3;
    const bool u8  = (g_valid_is_u8 != 0);
    const int* kvalid32 = (const int*)kvalid;

    // pack fp16 B fragments (validated layout)
    for (int i = tid; i < KVOL * 512; i += THREADS) {
        int tap = i >> 9, d = i & 511;
        int p = d >> 7, ln = (d >> 2) & 31, q = d & 3;
        int kc = p >> 1;
        int nt = (p & 1) * 2 + (q >> 1);
        int tg = ln & 3, gd = ln >> 2;
        int k = kc * 16 + 2 * tg + ((q & 1) ? 8 : 0);
        const float* wrow = weight + (size_t)tap * 1024;
        ((uint32_t*)smem)[(size_t)tap * 512 + d] =
            h2pack(wrow[k * 32 + nt * 8 + gd], wrow[(k + 1) * 32 + nt * 8 + gd]);
    }
    // bias into smem (frees 8 regs vs register-resident fragments)
    if (tid < 32) ((float*)(smem + OFF_BIAS))[tid] = bias[tid];
    __syncthreads();

    const int ntiles = (N + ROWS_W - 1) / ROWS_W;
    const int TW     = gridDim.x * WARPS;
    const int gw     = blockIdx.x * WARPS + w;

    int myT = 0;
    for (int t = gw; t < ntiles; t += TW) myT++;
    const int total = myT * KVOL;
    if (total == 0) return;

    const uint32_t aBase = sb + OFF_A + (uint32_t)(w * NSTAGE) * SLICE;
    const char*    fbase = (const char*)g_feath;

    const uint32_t dst0 = (uint32_t)r8 * 64 + (uint32_t)ch * 16;
    const uint32_t dst1 = dst0 + 512;

    auto load_idx = [&](int S, int tap, Pref& P) {
        P.idx0 = 0; P.idx1 = 0; P.n0 = 0; P.n1 = 0;
        int g0 = S * ROWS_W + r8, g1 = g0 + 8;
        if (S < ntiles) {
            size_t o = (size_t)tap * N;
            if (g0 < N) {
                P.idx0 = kidx[o + g0];
                P.n0 = (u8 ? (kvalid[o + g0] != 0) : (kvalid32[o + g0] != 0)) ? 16u : 0u;
            }
            if (g1 < N) {
                P.idx1 = kidx[o + g1];
                P.n1 = (u8 ? (kvalid[o + g1] != 0) : (kvalid32[o + g1] != 0)) ? 16u : 0u;
            }
        }
    };
    auto issue = [&](const Pref& P, int stage) {
        uint32_t ab = aBase + (uint32_t)stage * SLICE;
        cp16(ab + dst0, fbase + ((size_t)(uint32_t)P.idx0 << 6) + (ch << 4), P.n0);
        cp16(ab + dst1, fbase + ((size_t)(uint32_t)P.idx1 << 6) + (ch << 4), P.n1);
    };

    // ---- prologue: jobs 0..2 issued, idx(job3) prefetched ----
    Pref Pa;
    load_idx(gw, 0, Pa);
    issue(Pa, 0); CP_COMMIT();
    if (total > 1) { load_idx(gw, 1, Pa); issue(Pa, 1); }
    CP_COMMIT();
    if (total > 2) { load_idx(gw, 2, Pa); issue(Pa, 2); }
    CP_COMMIT();
    if (total > 3) load_idx(gw, 3, Pa);

    int ptap = 4, pS = gw;
    while (ptap >= KVOL) { ptap -= KVOL; pS += TW; }
    int ctap = 0, cS = gw;

    float acc[4][4];
    #pragma unroll
    for (int nt = 0; nt < 4; nt++)
        #pragma unroll
        for (int r = 0; r < 4; r++) acc[nt][r] = 0.0f;

    for (int jl = 0; jl < total; jl++) {
        CP_WAIT2();
        __syncwarp();

        if (jl + 3 < total) issue(Pa, (jl + 3) & (NSTAGE - 1));
        CP_COMMIT();

        if (jl + 4 < total) {
            load_idx(pS, ptap, Pa);
            if (++ptap == KVOL) { ptap = 0; pS += TW; }
        }

        const char* Ab = (const char*)smem + OFF_A
                       + (size_t)(w * NSTAGE + (jl & (NSTAGE - 1))) * SLICE;

        // A fragments: 2x LDS.128, contiguous, conflict-free
        uint4 L = *(const uint4*)(Ab + (size_t)gid * 64 + tig * 16);
        uint4 M = *(const uint4*)(Ab + (size_t)(gid + 8) * 64 + tig * 16);

        const uint4* wp = (const uint4*)(smem + (size_t)ctap * W_TAP);

        #pragma unroll
        for (int kc = 0; kc < 2; kc++) {
            uint4 bf0 = wp[(kc * 2 + 0) * 32 + lane];
            uint4 bf1 = wp[(kc * 2 + 1) * 32 + lane];
            uint32_t a0 = kc ? L.z : L.x;
            uint32_t a2 = kc ? L.w : L.y;
            uint32_t a1 = kc ? M.z : M.x;
            uint32_t a3 = kc ? M.w : M.y;
            mma_f16(acc[0][0], acc[0][1], acc[0][2], acc[0][3], a0, a1, a2, a3, bf0.x, bf0.y);
            mma_f16(acc[1][0], acc[1][1], acc[1][2], acc[1][3], a0, a1, a2, a3, bf0.z, bf0.w);
            mma_f16(acc[2][0], acc[2][1], acc[2][2], acc[2][3], a0, a1, a2, a3, bf1.x, bf1.y);
            mma_f16(acc[3][0], acc[3][1], acc[3][2], acc[3][3], a0, a1, a2, a3, bf1.z, bf1.w);
        }

        if (++ctap == KVOL) {
            int gr = cS * ROWS_W + gid;
            const float* bsm = (const float*)(smem + OFF_BIAS);
            #pragma unroll
            for (int nt = 0; nt < 4; nt++) {
                int col = nt * 8 + tig * 2;
                float2 bv = *(const float2*)(bsm + col);
                if (gr < N) {
                    float2 o = { acc[nt][0] + bv.x, acc[nt][1] + bv.y };
                    *(float2*)(out + (size_t)gr * COUT + col) = o;
                }
                if (gr + 8 < N) {
                    float2 o = { acc[nt][2] + bv.x, acc[nt][3] + bv.y };
                    *(float2*)(out + (size_t)(gr + 8) * COUT + col) = o;
                }
                acc[nt][0] = acc[nt][1] = acc[nt][2] = acc[nt][3] = 0.0f;
            }
            ctap = 0;
            cS += TW;
        }
    }
}

extern "C" void kernel_launch(void* const* d_in, const int* in_sizes, int n_in,
                              void* d_out, int out_size) {
    const float*         feat   = (const float*)d_in[0];          // [N, 32]
    const float*         weight = (const float*)d_in[1];          // [27, 32, 32]
    const float*         bias   = (const float*)d_in[2];          // [32]
    const int*           kidx   = (const int*)d_in[3];            // [27, N]
    const unsigned char* kvalid = (const unsigned char*)d_in[4];  // [27, N] bool
    float* out = (float*)d_out;

    const int N = in_sizes[0] / CIN;

    int sms = 148;
    cudaDeviceGetAttribute(&sms, cudaDevAttrMultiProcessorCount, 0);

    cudaFuncSetAttribute(spconv_mma, cudaFuncAttributeMaxDynamicSharedMemorySize, SMEM_TOTAL);

    prepass<<<sms * 8, 256>>>(feat, kvalid, N);
    spconv_mma<<<sms, THREADS, SMEM_TOTAL>>>(weight, bias, kidx, kvalid, out, N);
}

// round 11
// speedup vs baseline: 1.9360x; 1.0226x over previous
#include <cuda_runtime.h>
#include <cuda_fp16.h>
#include <cstdint>

#define CIN     32
#define COUT    32
#define KVOL    27
#define WARPS   24
#define THREADS 768
#define NSTAGE  3
#define ROWS_W  32
#define SLICE   2048                    // 32 rows * 64 B
#define W_TAP   2048
#define WBYTES  (KVOL * W_TAP)          // 55296
#define OFF_BIAS WBYTES
#define OFF_A   (WBYTES + 128)
#define SMEM_TOTAL (OFF_A + WARPS * NSTAGE * SLICE)    // 202880
#define CAP     1000000

// K-permuted fp16 feature table (64 MB device scratch)
__device__ __align__(16) __half g_feath[(size_t)CAP * 32];
__device__ int g_valid_is_u8;

__device__ __forceinline__ uint32_t smem_u32(const void* p) {
    uint32_t a;
    asm("{ .reg .u64 t; cvta.to.shared.u64 t, %1; cvt.u32.u64 %0, t; }" : "=r"(a) : "l"(p));
    return a;
}
__device__ __forceinline__ void cp16(uint32_t dst, const void* src, uint32_t nbytes) {
    asm volatile("cp.async.cg.shared.global [%0], [%1], 16, %2;"
                 :: "r"(dst), "l"(src), "r"(nbytes) : "memory");
}
#define CP_COMMIT() asm volatile("cp.async.commit_group;" ::: "memory")
#define CP_WAIT1()  asm volatile("cp.async.wait_group 1;" ::: "memory")

__device__ __forceinline__ uint32_t h2pack(float a, float b) {
    __half2 h = __floats2half2_rn(a, b);
    return *(uint32_t*)&h;
}
__device__ __forceinline__ void mma_f16(float& d0, float& d1, float& d2, float& d3,
                                        uint32_t a0, uint32_t a1, uint32_t a2, uint32_t a3,
                                        uint32_t b0, uint32_t b1) {
    asm volatile(
        "mma.sync.aligned.m16n8k16.row.col.f32.f16.f16.f32 "
        "{%0,%1,%2,%3}, {%4,%5,%6,%7}, {%8,%9}, {%0,%1,%2,%3};"
        : "+f"(d0), "+f"(d1), "+f"(d2), "+f"(d3)
        : "r"(a0), "r"(a1), "r"(a2), "r"(a3), "r"(b0), "r"(b1));
}

// prepass: permuted fp16 table (validated) + valid-dtype detection
__global__ void prepass(const float* __restrict__ feat,
                        const unsigned char* __restrict__ kvalid, int N) {
    if (blockIdx.x == 0 && threadIdx.x < 32) {
        int nz = 0;
        for (int i = threadIdx.x; i < 4096; i += 32)
            if ((i & 3) && kvalid[i]) nz = 1;
        nz = __any_sync(0xffffffffu, nz);
        if (threadIdx.x == 0) g_valid_is_u8 = nz;
    }
    int stride = gridDim.x * blockDim.x;
    int total = N * 8;
    for (int i = blockIdx.x * blockDim.x + threadIdx.x; i < total; i += stride) {
        int n = i >> 3, s = i & 7;
        int tig = s >> 1, kc = s & 1;
        const float* src = feat + (size_t)n * 32 + kc * 16 + 2 * tig;
        uint2 o;
        o.x = h2pack(src[0], src[1]);
        o.y = h2pack(src[8], src[9]);
        ((uint2*)g_feath)[(size_t)n * 8 + tig * 2 + kc] = o;
    }
}

struct Pref { int idx[4]; uint32_t n[4]; };

// ---------------- main kernel ----------------
__global__ void __launch_bounds__(THREADS, 1)
spconv_mma(const float* __restrict__ weight,
           const float* __restrict__ bias,
           const int* __restrict__ kidx,
           const unsigned char* __restrict__ kvalid,
           float* __restrict__ out,
           int N)
{
    extern __shared__ __align__(16) char smem[];
    const uint32_t sb = smem_u32(smem);

    const int tid  = threadIdx.x;
    const int w    = tid >> 5;
    const int lane = tid & 31;
    const int gid  = lane >> 2;
    const int tig  = lane & 3;
    const int r8   = lane >> 2;   // gather row base 0..7
    const int ch   = lane & 3;    // 16B chunk 0..3
    const bool u8  = (g_valid_is_u8 != 0);
    const int* kvalid32 = (const int*)kvalid;

    // pack fp16 B fragments (validated layout)
    for (int i = tid; i < KVOL * 512; i += THREADS) {
        int tap = i >> 9, d = i & 511;
        int p = d >> 7, ln = (d >> 2) & 31, q = d & 3;
        int kc = p >> 1;
        int nt = (p & 1) * 2 + (q >> 1);
        int tg = ln & 3, gd = ln >> 2;
        int k = kc * 16 + 2 * tg + ((q & 1) ? 8 : 0);
        const float* wrow = weight + (size_t)tap * 1024;
        ((uint32_t*)smem)[(size_t)tap * 512 + d] =
            h2pack(wrow[k * 32 + nt * 8 + gd], wrow[(k + 1) * 32 + nt * 8 + gd]);
    }
    if (tid < 32) ((float*)(smem + OFF_BIAS))[tid] = bias[tid];
    __syncthreads();

    const int ntiles = (N + ROWS_W - 1) / ROWS_W;
    const int TW     = gridDim.x * WARPS;            // total warps
    const int gw     = blockIdx.x * WARPS + w;

    int myT = 0;
    for (int t = gw; t < ntiles; t += TW) myT++;
    const int total = myT * KVOL;
    if (total == 0) return;

    const uint32_t aBase = sb + OFF_A + (uint32_t)(w * NSTAGE) * SLICE;
    const char*    fbase = (const char*)g_feath;
    const uint32_t dst0  = (uint32_t)r8 * 64 + (uint32_t)ch * 16;

    // incremental kmap cursor (prefetch stream)
    int lTap = 0;
    int lRow = gw * ROWS_W;            // global row base of prefetch tile
    int lOff = lRow;                   // = lTap*N + lRow (element offset into kmap)
    const int wrapAdj = TW * ROWS_W - (KVOL - 1) * N;

    auto load_idx = [&](Pref& P) {
        #pragma unroll
        for (int q = 0; q < 4; q++) {
            int g = lRow + r8 + 8 * q;
            int o = lOff + r8 + 8 * q;
            int id = 0; bool va = false;
            if (g < N) {
                id = kidx[o];
                va = u8 ? (kvalid[o] != 0) : (kvalid32[o] != 0);
            }
            P.idx[q] = id;
            P.n[q] = va ? 16u : 0u;
        }
        if (++lTap == KVOL) { lTap = 0; lOff += wrapAdj; lRow += TW * ROWS_W; }
        else lOff += N;
    };
    auto issue = [&](const Pref& P, int stage) {
        uint32_t ab = aBase + (uint32_t)stage * SLICE + dst0;
        #pragma unroll
        for (int q = 0; q < 4; q++)
            cp16(ab + q * 512u, fbase + ((size_t)(uint32_t)P.idx[q] << 6) + (ch << 4), P.n[q]);
    };

    // ---- prologue: jobs 0,1 issued; job 2 idx prefetched ----
    Pref Pa;
    load_idx(Pa);
    issue(Pa, 0); CP_COMMIT();
    if (total > 1) { load_idx(Pa); issue(Pa, 1); }
    CP_COMMIT();
    if (total > 2) load_idx(Pa);

    int pstage = 2, cstage = 0;
    int ctap = 0;
    int cRow = gw * ROWS_W;            // compute tile row base

    float acc[2][4][4];
    #pragma unroll
    for (int s = 0; s < 2; s++)
        #pragma unroll
        for (int nt = 0; nt < 4; nt++)
            #pragma unroll
            for (int r = 0; r < 4; r++) acc[s][nt][r] = 0.0f;

    for (int jl = 0; jl < total; jl++) {
        CP_WAIT1();
        __syncwarp();

        if (jl + 2 < total) {
            issue(Pa, pstage);
            if (++pstage == NSTAGE) pstage = 0;
        }
        CP_COMMIT();

        if (jl + 3 < total) load_idx(Pa);

        const char* Ab = (const char*)smem + OFF_A
                       + (size_t)(w * NSTAGE + cstage) * SLICE;
        if (++cstage == NSTAGE) cstage = 0;

        // B fragments: once per tap, reused by both subtiles
        const uint4* wp = (const uint4*)(smem + (size_t)ctap * W_TAP);
        uint4 bf0 = wp[0 * 32 + lane];   // kc0, nt 0/1
        uint4 bf1 = wp[1 * 32 + lane];   // kc0, nt 2/3
        uint4 bf2 = wp[2 * 32 + lane];   // kc1, nt 0/1
        uint4 bf3 = wp[3 * 32 + lane];   // kc1, nt 2/3

        #pragma unroll
        for (int s = 0; s < 2; s++) {
            uint4 L = *(const uint4*)(Ab + (size_t)(s * 16 + gid) * 64 + tig * 16);
            uint4 M = *(const uint4*)(Ab + (size_t)(s * 16 + gid + 8) * 64 + tig * 16);
            // kc = 0
            mma_f16(acc[s][0][0], acc[s][0][1], acc[s][0][2], acc[s][0][3],
                    L.x, M.x, L.y, M.y, bf0.x, bf0.y);
            mma_f16(acc[s][1][0], acc[s][1][1], acc[s][1][2], acc[s][1][3],
                    L.x, M.x, L.y, M.y, bf0.z, bf0.w);
            mma_f16(acc[s][2][0], acc[s][2][1], acc[s][2][2], acc[s][2][3],
                    L.x, M.x, L.y, M.y, bf1.x, bf1.y);
            mma_f16(acc[s][3][0], acc[s][3][1], acc[s][3][2], acc[s][3][3],
                    L.x, M.x, L.y, M.y, bf1.z, bf1.w);
            // kc = 1
            mma_f16(acc[s][0][0], acc[s][0][1], acc[s][0][2], acc[s][0][3],
                    L.z, M.z, L.w, M.w, bf2.x, bf2.y);
            mma_f16(acc[s][1][0], acc[s][1][1], acc[s][1][2], acc[s][1][3],
                    L.z, M.z, L.w, M.w, bf2.z, bf2.w);
            mma_f16(acc[s][2][0], acc[s][2][1], acc[s][2][2], acc[s][2][3],
                    L.z, M.z, L.w, M.w, bf3.x, bf3.y);
            mma_f16(acc[s][3][0], acc[s][3][1], acc[s][3][2], acc[s][3][3],
                    L.z, M.z, L.w, M.w, bf3.z, bf3.w);
        }

        if (++ctap == KVOL) {
            const float* bsm = (const float*)(smem + OFF_BIAS);
            #pragma unroll
            for (int s = 0; s < 2; s++) {
                int gr = cRow + s * 16 + gid;
                #pragma unroll
                for (int nt = 0; nt < 4; nt++) {
                    int col = nt * 8 + tig * 2;
                    float2 bv = *(const float2*)(bsm + col);
                    if (gr < N) {
                        float2 o = { acc[s][nt][0] + bv.x, acc[s][nt][1] + bv.y };
                        *(float2*)(out + (size_t)gr * COUT + col) = o;
                    }
                    if (gr + 8 < N) {
                        float2 o = { acc[s][nt][2] + bv.x, acc[s][nt][3] + bv.y };
                        *(float2*)(out + (size_t)(gr + 8) * COUT + col) = o;
                    }
                    acc[s][nt][0] = acc[s][nt][1] = acc[s][nt][2] = acc[s][nt][3] = 0.0f;
                }
            }
            ctap = 0;
            cRow += TW * ROWS_W;
        }
    }
}

extern "C" void kernel_launch(void* const* d_in, const int* in_sizes, int n_in,
                              void* d_out, int out_size) {
    const float*         feat   = (const float*)d_in[0];          // [N, 32]
    const float*         weight = (const float*)d_in[1];          // [27, 32, 32]
    const float*         bias   = (const float*)d_in[2];          // [32]
    const int*           kidx   = (const int*)d_in[3];            // [27, N]
    const unsigned char* kvalid = (const unsigned char*)d_in[4];  // [27, N] bool
    float* out = (float*)d_out;

    const int N = in_sizes[0] / CIN;

    int sms = 148;
    cudaDeviceGetAttribute(&sms, cudaDevAttrMultiProcessorCount, 0);

    cudaFuncSetAttribute(spconv_mma, cudaFuncAttributeMaxDynamicSharedMemorySize, SMEM_TOTAL);

    prepass<<<sms * 8, 256>>>(feat, kvalid, N);
    spconv_mma<<<sms, THREADS, SMEM_TOTAL>>>(weight, bias, kidx, kvalid, out, N);
}

// round 12
// speedup vs baseline: 2.7366x; 1.4135x over previous
#include <cuda_runtime.h>
#include <cuda_fp16.h>
#include <cstdint>

#define CIN     32
#define COUT    32
#define KVOL    27
#define WARPS   24
#define THREADS 768
#define NSTAGE  3
#define ROWS_W  32
#define SLICE   2048                    // 32 rows * 64 B
#define W_TAP   2048
#define WBYTES  (KVOL * W_TAP)          // 55296
#define OFF_BIAS WBYTES
#define OFF_A   (WBYTES + 128)          // 55424
#define OFF_IDX (OFF_A + WARPS * NSTAGE * SLICE)       // 202880
#define NSLOT   4
#define SLOTB   256                     // 128B idx + 128B valid
#define SMEM_TOTAL (OFF_IDX + WARPS * NSLOT * SLOTB)   // 227456
#define CAP     1000000

// K-permuted fp16 feature table (64 MB device scratch)
__device__ __align__(16) __half g_feath[(size_t)CAP * 32];
__device__ int g_valid_is_u8;

__device__ __forceinline__ uint32_t smem_u32(const void* p) {
    uint32_t a;
    asm("{ .reg .u64 t; cvta.to.shared.u64 t, %1; cvt.u32.u64 %0, t; }" : "=r"(a) : "l"(p));
    return a;
}
__device__ __forceinline__ void cp16(uint32_t dst, const void* src, uint32_t nbytes) {
    asm volatile("cp.async.cg.shared.global [%0], [%1], 16, %2;"
                 :: "r"(dst), "l"(src), "r"(nbytes) : "memory");
}
#define CP_COMMIT() asm volatile("cp.async.commit_group;" ::: "memory")
#define CP_WAIT1()  asm volatile("cp.async.wait_group 1;" ::: "memory")

__device__ __forceinline__ uint32_t h2pack(float a, float b) {
    __half2 h = __floats2half2_rn(a, b);
    return *(uint32_t*)&h;
}
__device__ __forceinline__ void mma_f16(float& d0, float& d1, float& d2, float& d3,
                                        uint32_t a0, uint32_t a1, uint32_t a2, uint32_t a3,
                                        uint32_t b0, uint32_t b1) {
    asm volatile(
        "mma.sync.aligned.m16n8k16.row.col.f32.f16.f16.f32 "
        "{%0,%1,%2,%3}, {%4,%5,%6,%7}, {%8,%9}, {%0,%1,%2,%3};"
        : "+f"(d0), "+f"(d1), "+f"(d2), "+f"(d3)
        : "r"(a0), "r"(a1), "r"(a2), "r"(a3), "r"(b0), "r"(b1));
}

// prepass: permuted fp16 table (validated) + valid-dtype detection
__global__ void prepass(const float* __restrict__ feat,
                        const unsigned char* __restrict__ kvalid, int N) {
    if (blockIdx.x == 0 && threadIdx.x < 32) {
        int nz = 0;
        for (int i = threadIdx.x; i < 4096; i += 32)
            if ((i & 3) && kvalid[i]) nz = 1;
        nz = __any_sync(0xffffffffu, nz);
        if (threadIdx.x == 0) g_valid_is_u8 = nz;
    }
    int stride = gridDim.x * blockDim.x;
    int total = N * 8;
    for (int i = blockIdx.x * blockDim.x + threadIdx.x; i < total; i += stride) {
        int n = i >> 3, s = i & 7;
        int tig = s >> 1, kc = s & 1;
        const float* src = feat + (size_t)n * 32 + kc * 16 + 2 * tig;
        uint2 o;
        o.x = h2pack(src[0], src[1]);
        o.y = h2pack(src[8], src[9]);
        ((uint2*)g_feath)[(size_t)n * 8 + tig * 2 + kc] = o;
    }
}

// ---------------- main kernel ----------------
__global__ void __launch_bounds__(THREADS, 1)
spconv_mma(const float* __restrict__ weight,
           const float* __restrict__ bias,
           const int* __restrict__ kidx,
           const unsigned char* __restrict__ kvalid,
           float* __restrict__ out,
           int N)
{
    extern __shared__ __align__(16) char smem[];
    const uint32_t sb = smem_u32(smem);

    const int tid  = threadIdx.x;
    const int w    = tid >> 5;
    const int lane = tid & 31;
    const int gid  = lane >> 2;
    const int tig  = lane & 3;
    const int r8   = lane >> 2;   // gather row base 0..7
    const int ch   = lane & 3;    // 16B chunk 0..3
    const bool u8  = (g_valid_is_u8 != 0);
    const int* kvalid32 = (const int*)kvalid;

    // pack fp16 B fragments (validated layout)
    for (int i = tid; i < KVOL * 512; i += THREADS) {
        int tap = i >> 9, d = i & 511;
        int p = d >> 7, ln = (d >> 2) & 31, q = d & 3;
        int kc = p >> 1;
        int nt = (p & 1) * 2 + (q >> 1);
        int tg = ln & 3, gd = ln >> 2;
        int k = kc * 16 + 2 * tg + ((q & 1) ? 8 : 0);
        const float* wrow = weight + (size_t)tap * 1024;
        ((uint32_t*)smem)[(size_t)tap * 512 + d] =
            h2pack(wrow[k * 32 + nt * 8 + gd], wrow[(k + 1) * 32 + nt * 8 + gd]);
    }
    if (tid < 32) ((float*)(smem + OFF_BIAS))[tid] = bias[tid];
    __syncthreads();

    const int ntiles = (N + ROWS_W - 1) / ROWS_W;
    const int TW     = gridDim.x * WARPS;
    const int gw     = blockIdx.x * WARPS + w;

    int myT = 0;
    for (int t = gw; t < ntiles; t += TW) myT++;
    const int total = myT * KVOL;
    if (total == 0) return;

    const uint32_t aBase  = sb + OFF_A + (uint32_t)(w * NSTAGE) * SLICE;
    const uint32_t ixBase = sb + OFF_IDX + (uint32_t)w * (NSLOT * SLOTB);
    const char*    idxsm  = smem + OFF_IDX + (size_t)w * (NSLOT * SLOTB);
    const char*    fbase  = (const char*)g_feath;
    const uint32_t dst0   = (uint32_t)r8 * 64 + (uint32_t)ch * 16;

    // idx-prefetch cursor: element offset into kmap for next idx-cp job
    int iTap = 2;                      // prologue cp's start at job 2
    int iOff = 2 * N + gw * ROWS_W;
    const int wrapAdj = TW * ROWS_W - (KVOL - 1) * N;

    auto idx_cp = [&](int slot) {
        uint32_t db = ixBase + (uint32_t)slot * SLOTB;
        if (lane < 8) {
            cp16(db + lane * 16, (const char*)kidx + (((size_t)iOff + lane * 4) << 2), 16u);
        } else if (lane < 16) {
            int l = lane - 8;
            if (u8) {
                if (l < 2) cp16(db + 128 + l * 16, (const char*)kvalid + (size_t)iOff + l * 16, 16u);
            } else {
                cp16(db + 128 + l * 16, (const char*)kvalid + (((size_t)iOff + l * 4) << 2), 16u);
            }
        }
        if (++iTap == KVOL) { iTap = 0; iOff += wrapAdj; }
        else iOff += N;
    };
    auto lds_idx = [&](int slot, int* iv, uint32_t* nv) {
        const char* p = idxsm + (size_t)slot * SLOTB;
        #pragma unroll
        for (int q = 0; q < 4; q++) {
            iv[q] = ((const int*)p)[r8 + 8 * q];
            bool va = u8 ? (((const unsigned char*)(p + 128))[r8 + 8 * q] != 0)
                         : (((const int*)(p + 128))[r8 + 8 * q] != 0);
            nv[q] = va ? 16u : 0u;
        }
    };
    auto gather = [&](const int* iv, const uint32_t* nv, int stage) {
        uint32_t ab = aBase + (uint32_t)stage * SLICE + dst0;
        #pragma unroll
        for (int q = 0; q < 4; q++)
            cp16(ab + q * 512u, fbase + ((size_t)(uint32_t)iv[q] << 6) + (ch << 4), nv[q]);
    };

    // ---- prologue ----
    // sync LDG idx for jobs 0 and 1 (taps 0,1 of first tile; total>=KVOL>4)
    {
        int iv[4]; uint32_t nv[4];
        #pragma unroll
        for (int job = 0; job < 2; job++) {
            int base = job * N + gw * ROWS_W;
            #pragma unroll
            for (int q = 0; q < 4; q++) {
                int o = base + r8 + 8 * q;
                iv[q] = kidx[o];
                bool va = u8 ? (kvalid[o] != 0) : (kvalid32[o] != 0);
                nv[q] = va ? 16u : 0u;
            }
            gather(iv, nv, job);       // stage = job (0,1)
            idx_cp(2 + job);           // slot 2, then slot 3 (jobs 2,3)
            CP_COMMIT();
        }
    }

    int pstage = 2, cstage = 0;
    int ctap = 0;
    int cRow = gw * ROWS_W;

    float acc[2][4][4];
    #pragma unroll
    for (int s = 0; s < 2; s++)
        #pragma unroll
        for (int nt = 0; nt < 4; nt++)
            #pragma unroll
            for (int r = 0; r < 4; r++) acc[s][nt][r] = 0.0f;

    for (int jl = 0; jl < total; jl++) {
        CP_WAIT1();
        __syncwarp();

        // gather for job jl+2 (its idx slot completed with group jl-2)
        if (jl + 2 < total) {
            int iv[4]; uint32_t nv[4];
            lds_idx((jl + 2) & (NSLOT - 1), iv, nv);
            gather(iv, nv, pstage);
            if (++pstage == NSTAGE) pstage = 0;
        }
        // idx prefetch for job jl+4
        if (jl + 4 < total) idx_cp((jl + 4) & (NSLOT - 1));
        CP_COMMIT();

        const char* Ab = (const char*)smem + OFF_A
                       + (size_t)(w * NSTAGE + cstage) * SLICE;
        if (++cstage == NSTAGE) cstage = 0;

        // B fragments: once per tap, reused by both subtiles
        const uint4* wp = (const uint4*)(smem + (size_t)ctap * W_TAP);
        uint4 bf0 = wp[0 * 32 + lane];
        uint4 bf1 = wp[1 * 32 + lane];
        uint4 bf2 = wp[2 * 32 + lane];
        uint4 bf3 = wp[3 * 32 + lane];

        #pragma unroll
        for (int s = 0; s < 2; s++) {
            uint4 L = *(const uint4*)(Ab + (size_t)(s * 16 + gid) * 64 + tig * 16);
            uint4 M = *(const uint4*)(Ab + (size_t)(s * 16 + gid + 8) * 64 + tig * 16);
            mma_f16(acc[s][0][0], acc[s][0][1], acc[s][0][2], acc[s][0][3],
                    L.x, M.x, L.y, M.y, bf0.x, bf0.y);
            mma_f16(acc[s][1][0], acc[s][1][1], acc[s][1][2], acc[s][1][3],
                    L.x, M.x, L.y, M.y, bf0.z, bf0.w);
            mma_f16(acc[s][2][0], acc[s][2][1], acc[s][2][2], acc[s][2][3],
                    L.x, M.x, L.y, M.y, bf1.x, bf1.y);
            mma_f16(acc[s][3][0], acc[s][3][1], acc[s][3][2], acc[s][3][3],
                    L.x, M.x, L.y, M.y, bf1.z, bf1.w);
            mma_f16(acc[s][0][0], acc[s][0][1], acc[s][0][2], acc[s][0][3],
                    L.z, M.z, L.w, M.w, bf2.x, bf2.y);
            mma_f16(acc[s][1][0], acc[s][1][1], acc[s][1][2], acc[s][1][3],
                    L.z, M.z, L.w, M.w, bf2.z, bf2.w);
            mma_f16(acc[s][2][0], acc[s][2][1], acc[s][2][2], acc[s][2][3],
                    L.z, M.z, L.w, M.w, bf3.x, bf3.y);
            mma_f16(acc[s][3][0], acc[s][3][1], acc[s][3][2], acc[s][3][3],
                    L.z, M.z, L.w, M.w, bf3.z, bf3.w);
        }

        if (++ctap == KVOL) {
            const float* bsm = (const float*)(smem + OFF_BIAS);
            #pragma unroll
            for (int s = 0; s < 2; s++) {
                int gr = cRow + s * 16 + gid;
                #pragma unroll
                for (int nt = 0; nt < 4; nt++) {
                    int col = nt * 8 + tig * 2;
                    float2 bv = *(const float2*)(bsm + col);
                    if (gr < N) {
                        float2 o = { acc[s][nt][0] + bv.x, acc[s][nt][1] + bv.y };
                        *(float2*)(out + (size_t)gr * COUT + col) = o;
                    }
                    if (gr + 8 < N) {
                        float2 o = { acc[s][nt][2] + bv.x, acc[s][nt][3] + bv.y };
                        *(float2*)(out + (size_t)(gr + 8) * COUT + col) = o;
                    }
                    acc[s][nt][0] = acc[s][nt][1] = acc[s][nt][2] = acc[s][nt][3] = 0.0f;
                }
            }
            ctap = 0;
            cRow += TW * ROWS_W;
        }
    }
}

extern "C" void kernel_launch(void* const* d_in, const int* in_sizes, int n_in,
                              void* d_out, int out_size) {
    const float*         feat   = (const float*)d_in[0];          // [N, 32]
    const float*         weight = (const float*)d_in[1];          // [27, 32, 32]
    const float*         bias   = (const float*)d_in[2];          // [32]
    const int*           kidx   = (const int*)d_in[3];            // [27, N]
    const unsigned char* kvalid = (const unsigned char*)d_in[4];  // [27, N] bool
    float* out = (float*)d_out;

    const int N = in_sizes[0] / CIN;

    int sms = 148;
    cudaDeviceGetAttribute(&sms, cudaDevAttrMultiProcessorCount, 0);

    cudaFuncSetAttribute(spconv_mma, cudaFuncAttributeMaxDynamicSharedMemorySize, SMEM_TOTAL);

    prepass<<<sms * 8, 256>>>(feat, kvalid, N);
    spconv_mma<<<sms, THREADS, SMEM_TOTAL>>>(weight, bias, kidx, kvalid, out, N);
}